// round 1
// baseline (speedup 1.0000x reference)
#include <cuda_runtime.h>
#include <cstdint>
#include <math.h>

#define N_NODES   100000
#define N_EDGES   200000
#define NNZ       2000000
#define DIM       64
#define HID       32
#define K_KEEP    1000000

// ---------------- device scratch (no allocations allowed) ----------------
struct Ctrl {
    unsigned p1, p2, Tbits;
    int rank;
    int skip;
    int ib;
    int cutoff;
};

__device__ __align__(16) float g_xa[N_NODES * HID];   // x @ W1[:64] + b1
__device__ __align__(16) float g_xb[N_NODES * HID];   // x @ W1[64:]
__device__ __align__(16) float g_eb[N_EDGES * HID];   // segment sums of xb
__device__ int      g_cnt[N_EDGES];
__device__ float    g_inv[N_EDGES];
__device__ float    g_sum_p[N_EDGES];
__device__ float    g_sum_s[N_EDGES];
__device__ unsigned g_hist[5][2048];
__device__ Ctrl     g_ctrl;

// ---------------- zero scratch ----------------
__global__ void k_zero() {
    int tid = blockIdx.x * blockDim.x + threadIdx.x;
    int nt  = gridDim.x * blockDim.x;
    for (int i = tid; i < N_EDGES * HID; i += nt) g_eb[i] = 0.0f;
    for (int i = tid; i < N_EDGES; i += nt) {
        g_cnt[i] = 0; g_sum_p[i] = 0.0f; g_sum_s[i] = 0.0f;
    }
    for (int i = tid; i < 5 * 2048; i += nt) ((unsigned*)g_hist)[i] = 0u;
    if (tid == 0) {
        g_ctrl.p1 = 0; g_ctrl.p2 = 0; g_ctrl.Tbits = 0;
        g_ctrl.rank = 0; g_ctrl.skip = 0; g_ctrl.ib = 0; g_ctrl.cutoff = 0;
    }
}

// ---------------- per-node projections: xa = x@W1a + b1, xb = x@W1b ----------------
__global__ void k_proj(const float* __restrict__ x,
                       const float* __restrict__ W1,
                       const float* __restrict__ b1) {
    __shared__ float sW[128 * 32];
    for (int i = threadIdx.x; i < 128 * 32; i += blockDim.x) sW[i] = W1[i];
    __syncthreads();
    int lane = threadIdx.x & 31;
    int warp = threadIdx.x >> 5;
    int wpb  = blockDim.x >> 5;
    float bb = b1[lane];
    for (int row = blockIdx.x * wpb + warp; row < N_NODES; row += gridDim.x * wpb) {
        float x0 = x[row * 64 + lane];
        float x1 = x[row * 64 + 32 + lane];
        float aa = bb, ab = 0.0f;
#pragma unroll
        for (int k = 0; k < 32; k++) {
            float xv = __shfl_sync(0xffffffffu, x0, k);
            aa += xv * sW[k * 32 + lane];
            ab += xv * sW[(64 + k) * 32 + lane];
        }
#pragma unroll
        for (int k = 0; k < 32; k++) {
            float xv = __shfl_sync(0xffffffffu, x1, k);
            aa += xv * sW[(32 + k) * 32 + lane];
            ab += xv * sW[(96 + k) * 32 + lane];
        }
        g_xa[row * 32 + lane] = aa;
        g_xb[row * 32 + lane] = ab;
    }
}

// ---------------- scatter xb into per-edge sums (v4 reductions) ----------------
__global__ void k_scatter(const int* __restrict__ V, const int* __restrict__ E) {
    int tid = blockIdx.x * blockDim.x + threadIdx.x;
    int g   = tid >> 3;
    int sub = tid & 7;
    if (g >= NNZ) return;
    int v = V[g], e = E[g];
    float4 val = *reinterpret_cast<const float4*>(&g_xb[v * 32 + sub * 4]);
    float* dst = &g_eb[e * 32 + sub * 4];
    asm volatile("red.global.add.v4.f32 [%0], {%1,%2,%3,%4};"
                 :: "l"(dst), "f"(val.x), "f"(val.y), "f"(val.z), "f"(val.w)
                 : "memory");
    if (sub == 0) atomicAdd(&g_cnt[e], 1);
}

// ---------------- reciprocal counts ----------------
__global__ void k_inv() {
    int e = blockIdx.x * blockDim.x + threadIdx.x;
    if (e < N_EDGES) {
        int c = g_cnt[e];
        g_inv[e] = 1.0f / (float)(c > 1 ? c : 1);
    }
}

// ---------------- fused MLP: probs + edge prob sums ----------------
__global__ void k_logits(const int* __restrict__ V, const int* __restrict__ E,
                         const float* __restrict__ W2, const float* __restrict__ b2,
                         float* __restrict__ out_probs) {
    int tid = blockIdx.x * blockDim.x + threadIdx.x;
    int g   = tid >> 3;
    int sub = tid & 7;
    if (g >= NNZ) return;
    int v = V[g], e = E[g];
    float  ic = g_inv[e];
    float4 a  = *reinterpret_cast<const float4*>(&g_xa[v * 32 + sub * 4]);
    float4 m  = *reinterpret_cast<const float4*>(&g_eb[e * 32 + sub * 4]);
    float4 w  = *reinterpret_cast<const float4*>(&W2[sub * 4]);
    float h0 = fmaxf(a.x + m.x * ic, 0.0f);
    float h1 = fmaxf(a.y + m.y * ic, 0.0f);
    float h2 = fmaxf(a.z + m.z * ic, 0.0f);
    float h3 = fmaxf(a.w + m.w * ic, 0.0f);
    float part = h0 * w.x + h1 * w.y + h2 * w.z + h3 * w.w;
    part += __shfl_xor_sync(0xffffffffu, part, 4);
    part += __shfl_xor_sync(0xffffffffu, part, 2);
    part += __shfl_xor_sync(0xffffffffu, part, 1);
    if (sub == 0) {
        float z = part + b2[0];
        float p = 1.0f / (1.0f + expf(-z));
        out_probs[g] = p;
        asm volatile("red.global.add.f32 [%0], %1;" :: "l"(&g_sum_p[e]), "f"(p) : "memory");
    }
}

// ---------------- selection: histograms ----------------
__global__ void k_hist(const float* __restrict__ probs, int phase) {
    __shared__ unsigned sh[2048];
    for (int i = threadIdx.x; i < 2048; i += blockDim.x) sh[i] = 0u;
    __syncthreads();
    unsigned p1 = g_ctrl.p1, p2 = g_ctrl.p2, Tb = g_ctrl.Tbits;
    int ib = g_ctrl.ib, skip = g_ctrl.skip;
    if (phase >= 3 && skip) return;   // uniform across all threads
    int tid = blockIdx.x * blockDim.x + threadIdx.x;
    int nt  = gridDim.x * blockDim.x;
    for (int i = tid; i < NNZ; i += nt) {
        unsigned bits = __float_as_uint(probs[i]);
        int b = -1;
        if (phase == 0)      b = (int)(bits >> 21);
        else if (phase == 1) { if ((bits >> 21) == p1) b = (int)((bits >> 10) & 2047u); }
        else if (phase == 2) { if ((bits >> 10) == p2) b = (int)(bits & 1023u); }
        else if (phase == 3) { if (bits == Tb) b = i >> 11; }
        else                 { if (bits == Tb && (i >> 11) == ib) b = i & 2047; }
        if (b >= 0) atomicAdd(&sh[b], 1u);
    }
    __syncthreads();
    for (int i = threadIdx.x; i < 2048; i += blockDim.x) {
        unsigned vv = sh[i];
        if (vv) atomicAdd(&g_hist[phase][i], vv);
    }
}

// ---------------- selection: scan + pick bucket ----------------
__global__ void k_scan(int phase) {
    __shared__ unsigned sA[2048], sB[2048];
    if (phase >= 3 && g_ctrl.skip) return;
    int n   = (phase == 2 || phase == 3) ? 1024 : 2048;
    int tid = threadIdx.x;  // blockDim = 1024
    const unsigned* hist = g_hist[phase];
    for (int i = tid; i < n; i += 1024) sA[i] = hist[i];
    __syncthreads();
    bool desc = (phase <= 2);
    unsigned *in = sA, *out = sB;
    for (int off = 1; off < n; off <<= 1) {
        for (int i = tid; i < n; i += 1024) {
            unsigned add = 0;
            if (desc) { if (i + off < n) add = in[i + off]; }
            else      { if (i >= off)    add = in[i - off]; }
            out[i] = in[i] + add;
        }
        __syncthreads();
        unsigned* t = in; in = out; out = t;
    }
    int rank = (phase == 0) ? K_KEEP : g_ctrl.rank;
    for (int i = tid; i < n; i += 1024) {
        bool hit;
        unsigned adj;
        if (desc) {
            unsigned nxt = (i + 1 < n) ? in[i + 1] : 0u;
            hit = ((int)in[i] >= rank) && ((int)nxt < rank);
            adj = nxt;
        } else {
            unsigned prv = (i > 0) ? in[i - 1] : 0u;
            hit = ((int)in[i] >= rank) && ((int)prv < rank);
            adj = prv;
        }
        if (hit) {
            if (phase == 0)      { g_ctrl.p1 = (unsigned)i; g_ctrl.rank = rank - (int)adj; }
            else if (phase == 1) { g_ctrl.p2 = (g_ctrl.p1 << 11) | (unsigned)i; g_ctrl.rank = rank - (int)adj; }
            else if (phase == 2) {
                g_ctrl.Tbits = (g_ctrl.p2 << 10) | (unsigned)i;
                int r   = rank - (int)adj;
                int neq = (int)(in[i] - adj);
                if (r >= neq) { g_ctrl.skip = 1; g_ctrl.cutoff = 0x7fffffff; }
                else          { g_ctrl.skip = 0; g_ctrl.rank = r; }
            }
            else if (phase == 3) { g_ctrl.ib = i; g_ctrl.rank = rank - (int)adj; }
            else                 { g_ctrl.cutoff = (g_ctrl.ib << 11) | i; }
        }
    }
}

// ---------------- hard/soft mask + edge soft sums ----------------
__global__ void k_mask(const int* __restrict__ E, const float* __restrict__ probs,
                       float* __restrict__ soft, float* __restrict__ hard) {
    int i = blockIdx.x * blockDim.x + threadIdx.x;
    if (i >= NNZ) return;
    float p = probs[i];
    unsigned bits = __float_as_uint(p);
    unsigned T = g_ctrl.Tbits;
    bool h = (bits > T) || (bits == T && i <= g_ctrl.cutoff);
    float hf = h ? 1.0f : 0.0f;
    float sf = h ? ((1.0f - p) + p) : 0.0f;   // straight-through forward value
    soft[i] = sf;
    hard[i] = hf;
    asm volatile("red.global.add.f32 [%0], %1;" :: "l"(&g_sum_s[E[i]]), "f"(sf) : "memory");
}

// ---------------- edge outputs ----------------
__global__ void k_edges(float* __restrict__ ep, float* __restrict__ es, float* __restrict__ eh) {
    int e = blockIdx.x * blockDim.x + threadIdx.x;
    if (e >= N_EDGES) return;
    int ci = g_cnt[e];
    float c = (float)(ci > 1 ? ci : 1);
    float ss = g_sum_s[e];
    ep[e] = g_sum_p[e] / c;
    es[e] = ss / c;
    eh[e] = (ss > 0.0f) ? 1.0f : 0.0f;
}

// ---------------- launcher ----------------
extern "C" void kernel_launch(void* const* d_in, const int* in_sizes, int n_in,
                              void* d_out, int out_size) {
    const float* x  = (const float*)d_in[0];
    const int*   V  = (const int*)d_in[1];
    const int*   E  = (const int*)d_in[2];
    const float* W1 = (const float*)d_in[3];
    const float* b1 = (const float*)d_in[4];
    const float* W2 = (const float*)d_in[5];
    const float* b2 = (const float*)d_in[6];

    float* out   = (float*)d_out;
    float* probs = out;
    float* soft  = out + NNZ;
    float* hard  = out + 2 * NNZ;
    float* ep    = out + 3 * NNZ;
    float* es    = ep + N_EDGES;
    float* eh    = es + N_EDGES;

    k_zero<<<512, 256>>>();
    k_proj<<<512, 256>>>(x, W1, b1);
    k_scatter<<<(NNZ * 8 + 255) / 256, 256>>>(V, E);
    k_inv<<<(N_EDGES + 255) / 256, 256>>>();
    k_logits<<<(NNZ * 8 + 255) / 256, 256>>>(V, E, W2, b2, probs);
    for (int ph = 0; ph < 5; ph++) {
        k_hist<<<512, 256>>>(probs, ph);
        k_scan<<<1, 1024>>>(ph);
    }
    k_mask<<<(NNZ + 255) / 256, 256>>>(E, probs, soft, hard);
    k_edges<<<(N_EDGES + 255) / 256, 256>>>(ep, es, eh);
}